// round 1
// baseline (speedup 1.0000x reference)
#include <cuda_runtime.h>

// LoRA linear, factored: out[row][o] = sum_r ( sum_k x[row][k]*A[r][k] ) * B[o][r]
// x: [16384, 4096] f32   A: [16, 4096] f32   B: [4096, 16] f32   out: [16384, 4096] f32

#define D 4096
#define R 16
#define TILE_ROWS 64
#define KC 512
#define AS_STRIDE 516   // 512 + 4 floats pad (bank-conflict-free LDS.128)

typedef unsigned long long u64;

// packed 2xfp32 FMA (Blackwell f32x2 pipe: 2x scalar FFMA throughput)
__device__ __forceinline__ u64 fma2(u64 a, u64 b, u64 c) {
    u64 d;
    asm("fma.rn.f32x2 %0, %1, %2, %3;" : "=l"(d) : "l"(a), "l"(b), "l"(c));
    return d;
}
__device__ __forceinline__ float hsum2(u64 v) {
    float lo, hi;
    asm("mov.b64 {%0, %1}, %2;" : "=f"(lo), "=f"(hi) : "l"(v));
    return lo + hi;
}

__global__ void __launch_bounds__(256, 2)
lora_fused(const float* __restrict__ x, const float* __restrict__ A,
           const float* __restrict__ B, float* __restrict__ out)
{
    __shared__ float as[R * AS_STRIDE];     // 33 KB: A chunk [16][512]
    __shared__ float ts[TILE_ROWS * R];     // 4 KB:  t tile [64][16]

    const int tid    = threadIdx.x;
    const int w      = tid >> 5;            // warp 0..7
    const int lane   = tid & 31;
    const int lane16 = lane & 15;
    const int half   = lane >> 4;           // r-half: lanes 0-15 -> r0..7, 16-31 -> r8..15
    const long rowBase = (long)blockIdx.x * TILE_ROWS;

    // ---------------- Phase 1: t = x @ A^T ----------------
    // Warp owns 8 rows (two groups of 4). Lane splits k (16 lanes x 4 floats)
    // and r (half-warps). f32x2 accumulators pair (k, k+1) -> no packing insts.
    for (int g = 0; g < 2; ++g) {
        const long row0 = rowBase + w * 8 + g * 4;
        u64 acc[4][8];
        #pragma unroll
        for (int i = 0; i < 4; ++i)
            #pragma unroll
            for (int j = 0; j < 8; ++j) acc[i][j] = 0ULL;

        for (int c = 0; c < D / KC; ++c) {
            __syncthreads();
            // cooperative load of A chunk [16][KC] into padded smem
            #pragma unroll
            for (int t4 = 0; t4 < (R * KC / 4) / 256; ++t4) {
                int idx = tid + t4 * 256;
                int r   = idx >> 7;        // / (KC/4 = 128)
                int kf  = idx & 127;
                float4 v = *(const float4*)(A + (long)r * D + c * KC + kf * 4);
                *(float4*)(as + r * AS_STRIDE + kf * 4) = v;
            }
            __syncthreads();

            #pragma unroll
            for (int it = 0; it < KC / 64; ++it) {
                const int kg = c * KC + it * 64 + lane16 * 4;  // global k
                const int ks = it * 64 + lane16 * 4;           // smem  k
                ulonglong2 xv[4];
                #pragma unroll
                for (int i = 0; i < 4; ++i)
                    xv[i] = *(const ulonglong2*)(x + (row0 + i) * D + kg);
                #pragma unroll
                for (int j = 0; j < 8; ++j) {
                    const int r = half * 8 + j;
                    ulonglong2 av = *(const ulonglong2*)(as + r * AS_STRIDE + ks);
                    #pragma unroll
                    for (int i = 0; i < 4; ++i) {
                        acc[i][j] = fma2(xv[i].x, av.x, acc[i][j]);
                        acc[i][j] = fma2(xv[i].y, av.y, acc[i][j]);
                    }
                }
            }
        }

        // collapse f32x2 lanes, butterfly-reduce across the 16 k-split lanes
        float s[4][8];
        #pragma unroll
        for (int i = 0; i < 4; ++i)
            #pragma unroll
            for (int j = 0; j < 8; ++j) {
                float v = hsum2(acc[i][j]);
                v += __shfl_xor_sync(0xffffffffu, v, 8);
                v += __shfl_xor_sync(0xffffffffu, v, 4);
                v += __shfl_xor_sync(0xffffffffu, v, 2);
                v += __shfl_xor_sync(0xffffffffu, v, 1);
                s[i][j] = v;
            }
        if (lane16 < 4) {
            int i = lane16;
            int trow = w * 8 + g * 4 + i;
            *(float4*)(ts + trow * R + half * 8) =
                make_float4(s[i][0], s[i][1], s[i][2], s[i][3]);
            *(float4*)(ts + trow * R + half * 8 + 4) =
                make_float4(s[i][4], s[i][5], s[i][6], s[i][7]);
        }
    }
    __syncthreads();

    // ---------------- Phase 2: out = t @ B^T ----------------
    // Lane owns 4 consecutive output cols; B[4][16] sub-block held in regs
    // (reused across 64 rows). t[row] broadcast from smem. STG.128 stores.
    for (int oc = 0; oc < 4; ++oc) {
        const int ob = oc * 1024 + w * 128 + lane * 4;
        u64 bb[4][8];
        #pragma unroll
        for (int j = 0; j < 4; ++j)
            #pragma unroll
            for (int q = 0; q < 2; ++q) {
                ulonglong2 v = *(const ulonglong2*)(B + (long)(ob + j) * R + q * 8);
                ulonglong2 v2 = *(const ulonglong2*)(B + (long)(ob + j) * R + q * 8 + 4);
                bb[j][4 * q + 0] = v.x;
                bb[j][4 * q + 1] = v.y;
                bb[j][4 * q + 2] = v2.x;
                bb[j][4 * q + 3] = v2.y;
            }

        for (int row = 0; row < TILE_ROWS; ++row) {
            u64 tt[8];
            #pragma unroll
            for (int q = 0; q < 4; ++q) {
                ulonglong2 v = *(const ulonglong2*)(ts + row * R + q * 4);
                tt[2 * q]     = v.x;
                tt[2 * q + 1] = v.y;
            }
            float res[4];
            #pragma unroll
            for (int j = 0; j < 4; ++j) {
                u64 acc = 0ULL;
                #pragma unroll
                for (int p = 0; p < 8; ++p)
                    acc = fma2(bb[j][p], tt[p], acc);
                res[j] = hsum2(acc);
            }
            *(float4*)(out + (rowBase + row) * (long)D + ob) =
                make_float4(res[0], res[1], res[2], res[3]);
        }
    }
}

extern "C" void kernel_launch(void* const* d_in, const int* in_sizes, int n_in,
                              void* d_out, int out_size) {
    const float* x = (const float*)d_in[0];   // [16384, 4096]
    const float* A = (const float*)d_in[1];   // [16, 4096]
    const float* B = (const float*)d_in[2];   // [4096, 16]
    float* out = (float*)d_out;               // [16384, 4096]

    const int rows = in_sizes[0] / D;         // 16384
    const int grid = rows / TILE_ROWS;        // 256
    lora_fused<<<grid, 256>>>(x, A, B, out);
}